// round 7
// baseline (speedup 1.0000x reference)
#include <cuda_runtime.h>
#include <cuda_fp16.h>

#define N_NODES 100000
#define N_EDGES 1600000
#define F 128
#define GRID2 296            // GEMM/stats grid
#define BN_EPS 1e-5f

// -------- scratch (static device allocations are allowed) --------
__device__ int      g_row_ptr[N_NODES + 1];
__device__ __half   g_y[(size_t)N_NODES * F];  // y = x @ W^T in fp16 (25.6 MB)
__device__ float    g_psum[F * GRID2];         // [feature][block]
__device__ float    g_psq [F * GRID2];
__device__ float    g_scale[F];
__device__ float    g_shift[F];

// packed fp32x2 fma (Blackwell; ptxas won't auto-fuse this)
__device__ __forceinline__ unsigned long long ffma2(unsigned long long a,
                                                    unsigned long long b,
                                                    unsigned long long c) {
    unsigned long long d;
    asm("fma.rn.f32x2 %0, %1, %2, %3;" : "=l"(d) : "l"(a), "l"(b), "l"(c));
    return d;
}

// ---------------- kernel 0: row_ptr via boundary scatter ----------------
__global__ void k_rowptr(const int* __restrict__ adj_row) {
    int e = blockIdx.x * blockDim.x + threadIdx.x;
    if (e >= N_EDGES) return;
    int r1 = __ldg(&adj_row[e]);
    if (e == 0) {
        for (int r = 0; r <= r1; r++) g_row_ptr[r] = 0;
    }
    int r2 = (e + 1 < N_EDGES) ? __ldg(&adj_row[e + 1]) : N_NODES;
    for (int r = r1 + 1; r <= r2; r++) g_row_ptr[r] = e + 1;
}

// ------------- kernel 1: dense GEMM y = x @ W^T, fp16 out -------------
// 256 threads: thread t owns feature f=t&127, k-half = t>>7 (64 k each).
// 8 nodes per tile; partial dot products joined via smem.
__global__ void __launch_bounds__(256, 2)
k_gemm(const float* __restrict__ x,
       const float* __restrict__ fc_w) {
    __shared__ float x_sm[8 * F];          // 4 KB
    __shared__ float red_sm[8 * 2 * F];    // 8 KB

    const int t    = threadIdx.x;
    const int f    = t & 127;
    const int half = t >> 7;

    // W[f][half*64 .. half*64+64) as 32 packed pairs (64 regs)
    unsigned long long w2[32];
    const unsigned long long* wrow = reinterpret_cast<const unsigned long long*>(
        fc_w + (size_t)f * F + half * 64);
#pragma unroll
    for (int i = 0; i < 32; i++) w2[i] = __ldg(&wrow[i]);

    const int r_ld  = t >> 5;      // row this thread loads (0..7)
    const int c4_ld = t & 31;      // float4 within row

    for (int n0 = blockIdx.x * 8; n0 < N_NODES; n0 += gridDim.x * 8) {
        const int nv = min(8, N_NODES - n0);

        __syncthreads();
        if (r_ld < nv)
            reinterpret_cast<float4*>(x_sm)[r_ld * 32 + c4_ld] =
                __ldg(&reinterpret_cast<const float4*>(x)[(size_t)(n0 + r_ld) * 32 + c4_ld]);
        __syncthreads();

        unsigned long long p0[8], p1[8];
#pragma unroll
        for (int r = 0; r < 8; r++) { p0[r] = 0ull; p1[r] = 0ull; }

        const ulonglong2* xs =
            reinterpret_cast<const ulonglong2*>(x_sm) + half * 8;  // 8 u2 = 32 floats... see idx below
        // row stride in ulonglong2 units: 128 floats / 4 = 32; half offset = half*16
#pragma unroll
        for (int j = 0; j < 16; j++) {
#pragma unroll
            for (int r = 0; r < 8; r++) {
                ulonglong2 aa = reinterpret_cast<const ulonglong2*>(x_sm)[r * 32 + half * 16 + j];
                p0[r] = ffma2(w2[2 * j],     aa.x, p0[r]);
                p1[r] = ffma2(w2[2 * j + 1], aa.y, p1[r]);
            }
        }
        (void)xs;

#pragma unroll
        for (int r = 0; r < 8; r++) {
            float2 f0 = *reinterpret_cast<float2*>(&p0[r]);
            float2 f1 = *reinterpret_cast<float2*>(&p1[r]);
            red_sm[(r * 2 + half) * F + f] = (f0.x + f0.y) + (f1.x + f1.y);
        }
        __syncthreads();

        if (t < F) {
#pragma unroll
            for (int r = 0; r < 8; r++) {
                if (r < nv) {
                    float hval = red_sm[(r * 2) * F + t] + red_sm[(r * 2 + 1) * F + t];
                    g_y[(size_t)(n0 + r) * F + t] = __float2half_rn(hval);
                }
            }
        }
    }
}

// ---------------- kernel 2: SpMM over y (fp16), + bias -> d_out ----------------
// warp per node; lane owns features [4*lane, 4*lane+4) (uint2 of 4 halfs).
__global__ void __launch_bounds__(256)
k_spmm(const int*   __restrict__ adj_col,
       const float* __restrict__ adj_val,
       const float* __restrict__ fc_b,
       float*       __restrict__ h_out) {
    const int n = (blockIdx.x * blockDim.x + threadIdx.x) >> 5;
    if (n >= N_NODES) return;
    const int lane = threadIdx.x & 31;

    const int s = g_row_ptr[n];
    const int e = g_row_ptr[n + 1];
    const uint2* yv = reinterpret_cast<const uint2*>(g_y);

    float4 acc = make_float4(0.f, 0.f, 0.f, 0.f);

    int k = s;
    for (; k + 16 <= e; k += 16) {
        int col = 0; float val = 0.f;
        if (lane < 16) {
            col = __ldg(&adj_col[k + lane]);
            val = __ldg(&adj_val[k + lane]);
        }
#pragma unroll
        for (int j = 0; j < 16; j++) {
            int   c = __shfl_sync(0xffffffffu, col, j);
            float v = __shfl_sync(0xffffffffu, val, j);
            uint2 raw = __ldg(&yv[(size_t)c * 32 + lane]);
            float2 f0 = __half22float2(*reinterpret_cast<__half2*>(&raw.x));
            float2 f1 = __half22float2(*reinterpret_cast<__half2*>(&raw.y));
            acc.x += v * f0.x; acc.y += v * f0.y;
            acc.z += v * f1.x; acc.w += v * f1.y;
        }
    }
    if (k < e) {
        int rem = e - k;                       // 1..15
        int col = 0; float val = 0.f;
        if (lane < rem) {
            col = __ldg(&adj_col[k + lane]);
            val = __ldg(&adj_val[k + lane]);
        }
#pragma unroll
        for (int j = 0; j < 15; j++) {
            if (j < rem) {
                int   c = __shfl_sync(0xffffffffu, col, j);
                float v = __shfl_sync(0xffffffffu, val, j);
                uint2 raw = __ldg(&yv[(size_t)c * 32 + lane]);
                float2 f0 = __half22float2(*reinterpret_cast<__half2*>(&raw.x));
                float2 f1 = __half22float2(*reinterpret_cast<__half2*>(&raw.y));
                acc.x += v * f0.x; acc.y += v * f0.y;
                acc.z += v * f1.x; acc.w += v * f1.y;
            }
        }
    }

    const float4 bb = __ldg(&reinterpret_cast<const float4*>(fc_b)[lane]);
    acc.x += bb.x; acc.y += bb.y; acc.z += bb.z; acc.w += bb.w;

    reinterpret_cast<float4*>(h_out)[(size_t)n * 32 + lane] = acc;
}

// ---------------- kernel 3a: BN partial sums over h ----------------
// 296 blocks x 256 threads; thread handles feature f=t&127, node parity t>>7.
__global__ void __launch_bounds__(256)
k_stats1(const float* __restrict__ h) {
    __shared__ float red[2 * F];
    const int t    = threadIdx.x;
    const int f    = t & 127;
    const int sub  = t >> 7;

    float s = 0.f, q = 0.f;
    for (int n = blockIdx.x * 2 + sub; n < N_NODES; n += gridDim.x * 2) {
        float v = __ldg(&h[(size_t)n * F + f]);
        s += v;
        q += v * v;
    }
    red[sub * F + f] = s;
    __syncthreads();
    if (sub == 0) {
        g_psum[f * GRID2 + blockIdx.x] = s + red[F + f];
    }
    __syncthreads();
    red[sub * F + f] = q;
    __syncthreads();
    if (sub == 0) {
        g_psq[f * GRID2 + blockIdx.x] = q + red[F + f];
    }
}

// ---------------- kernel 3b: finalize BN stats ----------------
__global__ void k_stats2(const float* __restrict__ bn_gamma,
                         const float* __restrict__ bn_beta) {
    __shared__ float ss[4], qq[4];
    const int o = blockIdx.x;
    const int t = threadIdx.x;

    float s = 0.f, q = 0.f;
    for (int b = t; b < GRID2; b += 128) {
        s += g_psum[o * GRID2 + b];
        q += g_psq [o * GRID2 + b];
    }
#pragma unroll
    for (int off = 16; off; off >>= 1) {
        s += __shfl_down_sync(0xffffffffu, s, off);
        q += __shfl_down_sync(0xffffffffu, q, off);
    }
    if ((t & 31) == 0) { ss[t >> 5] = s; qq[t >> 5] = q; }
    __syncthreads();
    if (t == 0) {
        s = ss[0] + ss[1] + ss[2] + ss[3];
        q = qq[0] + qq[1] + qq[2] + qq[3];
        const float inv_n = 1.0f / (float)N_NODES;
        float mean = s * inv_n;
        float var  = q * inv_n - mean * mean;
        float isd  = rsqrtf(var + BN_EPS);
        float sc   = __ldg(&bn_gamma[o]) * isd;
        g_scale[o] = sc;
        g_shift[o] = __ldg(&bn_beta[o]) - mean * sc;
    }
}

// ---------------- kernel 4: in-place normalize ----------------
__global__ void k_norm(float* __restrict__ h) {
    const size_t total = (size_t)N_NODES * F;
    size_t i = ((size_t)blockIdx.x * blockDim.x + threadIdx.x) * 4;
    if (i >= total) return;
    int o = (int)(i & (F - 1));
    float4 v  = *reinterpret_cast<float4*>(h + i);
    float4 sc = *reinterpret_cast<const float4*>(g_scale + o);
    float4 sh = *reinterpret_cast<const float4*>(g_shift + o);
    v.x = v.x * sc.x + sh.x;
    v.y = v.y * sc.y + sh.y;
    v.z = v.z * sc.z + sh.z;
    v.w = v.w * sc.w + sh.w;
    *reinterpret_cast<float4*>(h + i) = v;
}

// ---------------- launch (single stream) ----------------
extern "C" void kernel_launch(void* const* d_in, const int* in_sizes, int n_in,
                              void* d_out, int out_size) {
    const float* x        = (const float*)d_in[0];
    const int*   adj_row  = (const int*)  d_in[1];
    const int*   adj_col  = (const int*)  d_in[2];
    const float* adj_val  = (const float*)d_in[3];
    const float* fc_w     = (const float*)d_in[4];
    const float* fc_b     = (const float*)d_in[5];
    const float* bn_gamma = (const float*)d_in[6];
    const float* bn_beta  = (const float*)d_in[7];
    float* out = (float*)d_out;

    k_rowptr<<<(N_EDGES + 255) / 256, 256>>>(adj_row);
    k_gemm<<<GRID2, 256>>>(x, fc_w);
    k_spmm<<<(N_NODES * 32 + 255) / 256, 256>>>(adj_col, adj_val, fc_b, out);
    k_stats1<<<GRID2, 256>>>(out);
    k_stats2<<<F, 128>>>(bn_gamma, bn_beta);
    k_norm<<<(N_NODES * F / 4 + 255) / 256, 256>>>(out);
}

// round 9
// speedup vs baseline: 1.1308x; 1.1308x over previous
#include <cuda_runtime.h>
#include <cuda_fp16.h>

#define N_NODES 100000
#define N_EDGES 1600000
#define F 128
#define GRID2 296              // GEMM grid
#define NB_SPMM 12500          // spmm blocks: 8 nodes each, exact
#define BN_EPS 1e-5f

// -------- scratch (static device allocations are allowed) --------
__device__ int      g_row_ptr[N_NODES + 1];
__device__ __half   g_y[(size_t)N_NODES * F];      // y = x @ W^T fp16 (25.6 MB)
__device__ float    g_psum[(size_t)F * NB_SPMM];   // [feature][spmm block]
__device__ float    g_psq [(size_t)F * NB_SPMM];
__device__ float    g_scale[F];
__device__ float    g_shift[F];

// packed fp32x2 fma
__device__ __forceinline__ unsigned long long ffma2(unsigned long long a,
                                                    unsigned long long b,
                                                    unsigned long long c) {
    unsigned long long d;
    asm("fma.rn.f32x2 %0, %1, %2, %3;" : "=l"(d) : "l"(a), "l"(b), "l"(c));
    return d;
}

// ---------------- kernel 0: row_ptr via boundary scatter ----------------
__global__ void k_rowptr(const int* __restrict__ adj_row) {
    int e = blockIdx.x * blockDim.x + threadIdx.x;
    if (e >= N_EDGES) return;
    int r1 = __ldg(&adj_row[e]);
    if (e == 0) {
        for (int r = 0; r <= r1; r++) g_row_ptr[r] = 0;
    }
    int r2 = (e + 1 < N_EDGES) ? __ldg(&adj_row[e + 1]) : N_NODES;
    for (int r = r1 + 1; r <= r2; r++) g_row_ptr[r] = e + 1;
}

// ------------- kernel 1: dense GEMM y = x @ W^T, fp16 out -------------
// 256 threads: thread t owns feature f=t&127, k-half = t>>7 (64 k each).
__global__ void __launch_bounds__(256, 2)
k_gemm(const float* __restrict__ x,
       const float* __restrict__ fc_w) {
    __shared__ float x_sm[8 * F];          // 4 KB
    __shared__ float red_sm[8 * 2 * F];    // 8 KB

    const int t    = threadIdx.x;
    const int f    = t & 127;
    const int half = t >> 7;

    unsigned long long w2[32];
    const unsigned long long* wrow = reinterpret_cast<const unsigned long long*>(
        fc_w + (size_t)f * F + half * 64);
#pragma unroll
    for (int i = 0; i < 32; i++) w2[i] = __ldg(&wrow[i]);

    const int r_ld  = t >> 5;
    const int c4_ld = t & 31;

    for (int n0 = blockIdx.x * 8; n0 < N_NODES; n0 += gridDim.x * 8) {
        const int nv = min(8, N_NODES - n0);

        __syncthreads();
        if (r_ld < nv)
            reinterpret_cast<float4*>(x_sm)[r_ld * 32 + c4_ld] =
                __ldg(&reinterpret_cast<const float4*>(x)[(size_t)(n0 + r_ld) * 32 + c4_ld]);
        __syncthreads();

        unsigned long long p0[8], p1[8];
#pragma unroll
        for (int r = 0; r < 8; r++) { p0[r] = 0ull; p1[r] = 0ull; }

#pragma unroll
        for (int j = 0; j < 16; j++) {
#pragma unroll
            for (int r = 0; r < 8; r++) {
                ulonglong2 aa = reinterpret_cast<const ulonglong2*>(x_sm)[r * 32 + half * 16 + j];
                p0[r] = ffma2(w2[2 * j],     aa.x, p0[r]);
                p1[r] = ffma2(w2[2 * j + 1], aa.y, p1[r]);
            }
        }

#pragma unroll
        for (int r = 0; r < 8; r++) {
            float2 f0 = *reinterpret_cast<float2*>(&p0[r]);
            float2 f1 = *reinterpret_cast<float2*>(&p1[r]);
            red_sm[(r * 2 + half) * F + f] = (f0.x + f0.y) + (f1.x + f1.y);
        }
        __syncthreads();

        if (t < F) {
#pragma unroll
            for (int r = 0; r < 8; r++) {
                if (r < nv) {
                    float hval = red_sm[(r * 2) * F + t] + red_sm[(r * 2 + 1) * F + t];
                    g_y[(size_t)(n0 + r) * F + t] = __float2half_rn(hval);
                }
            }
        }
    }
}

// ------- kernel 2: SpMM over y (fp16) + bias -> d_out, fused BN partials -------
// 8 warps = 8 nodes per block; lane owns features [4*lane, 4*lane+4).
__global__ void __launch_bounds__(256)
k_spmm(const int*   __restrict__ adj_col,
       const float* __restrict__ adj_val,
       const float* __restrict__ fc_b,
       float*       __restrict__ h_out) {
    __shared__ float4 red_s[8][32];
    __shared__ float4 red_q[8][32];

    const int wid  = threadIdx.x >> 5;
    const int lane = threadIdx.x & 31;
    const int n    = blockIdx.x * 8 + wid;     // always < N_NODES (exact grid)

    const int s = g_row_ptr[n];
    const int e = g_row_ptr[n + 1];
    const uint2* yv = reinterpret_cast<const uint2*>(g_y);

    float4 acc = make_float4(0.f, 0.f, 0.f, 0.f);

    int k = s;
    for (; k + 16 <= e; k += 16) {
        int col = 0; float val = 0.f;
        if (lane < 16) {
            col = __ldg(&adj_col[k + lane]);
            val = __ldg(&adj_val[k + lane]);
        }
#pragma unroll
        for (int j = 0; j < 16; j++) {
            int   c = __shfl_sync(0xffffffffu, col, j);
            float v = __shfl_sync(0xffffffffu, val, j);
            uint2 raw = __ldg(&yv[(size_t)c * 32 + lane]);
            float2 f0 = __half22float2(*reinterpret_cast<__half2*>(&raw.x));
            float2 f1 = __half22float2(*reinterpret_cast<__half2*>(&raw.y));
            acc.x += v * f0.x; acc.y += v * f0.y;
            acc.z += v * f1.x; acc.w += v * f1.y;
        }
    }
    if (k < e) {
        int rem = e - k;                       // 1..15
        int col = 0; float val = 0.f;
        if (lane < rem) {
            col = __ldg(&adj_col[k + lane]);
            val = __ldg(&adj_val[k + lane]);
        }
#pragma unroll
        for (int j = 0; j < 15; j++) {
            if (j < rem) {
                int   c = __shfl_sync(0xffffffffu, col, j);
                float v = __shfl_sync(0xffffffffu, val, j);
                uint2 raw = __ldg(&yv[(size_t)c * 32 + lane]);
                float2 f0 = __half22float2(*reinterpret_cast<__half2*>(&raw.x));
                float2 f1 = __half22float2(*reinterpret_cast<__half2*>(&raw.y));
                acc.x += v * f0.x; acc.y += v * f0.y;
                acc.z += v * f1.x; acc.w += v * f1.y;
            }
        }
    }

    const float4 bb = __ldg(&reinterpret_cast<const float4*>(fc_b)[lane]);
    acc.x += bb.x; acc.y += bb.y; acc.z += bb.z; acc.w += bb.w;

    reinterpret_cast<float4*>(h_out)[(size_t)n * 32 + lane] = acc;

    // fused BN partials: reduce over the block's 8 nodes
    red_s[wid][lane] = acc;
    red_q[wid][lane] = make_float4(acc.x * acc.x, acc.y * acc.y,
                                   acc.z * acc.z, acc.w * acc.w);
    __syncthreads();
    if (wid == 0) {
        float4 s4 = red_s[0][lane], q4 = red_q[0][lane];
#pragma unroll
        for (int i = 1; i < 8; i++) {
            float4 a = red_s[i][lane], b = red_q[i][lane];
            s4.x += a.x; s4.y += a.y; s4.z += a.z; s4.w += a.w;
            q4.x += b.x; q4.y += b.y; q4.z += b.z; q4.w += b.w;
        }
        const int f0 = lane * 4;
        g_psum[(size_t)(f0 + 0) * NB_SPMM + blockIdx.x] = s4.x;
        g_psum[(size_t)(f0 + 1) * NB_SPMM + blockIdx.x] = s4.y;
        g_psum[(size_t)(f0 + 2) * NB_SPMM + blockIdx.x] = s4.z;
        g_psum[(size_t)(f0 + 3) * NB_SPMM + blockIdx.x] = s4.w;
        g_psq [(size_t)(f0 + 0) * NB_SPMM + blockIdx.x] = q4.x;
        g_psq [(size_t)(f0 + 1) * NB_SPMM + blockIdx.x] = q4.y;
        g_psq [(size_t)(f0 + 2) * NB_SPMM + blockIdx.x] = q4.z;
        g_psq [(size_t)(f0 + 3) * NB_SPMM + blockIdx.x] = q4.w;
    }
}

// ---------------- kernel 3: finalize BN stats ----------------
// one block per feature; 256 threads reduce NB_SPMM partials (coalesced).
__global__ void __launch_bounds__(256)
k_stats(const float* __restrict__ bn_gamma,
        const float* __restrict__ bn_beta) {
    __shared__ float ss[8], qq[8];
    const int o = blockIdx.x;
    const int t = threadIdx.x;

    float s = 0.f, q = 0.f;
    const float* ps = g_psum + (size_t)o * NB_SPMM;
    const float* pq = g_psq  + (size_t)o * NB_SPMM;
#pragma unroll 4
    for (int b = t; b < NB_SPMM; b += 256) {
        s += __ldg(&ps[b]);
        q += __ldg(&pq[b]);
    }
#pragma unroll
    for (int off = 16; off; off >>= 1) {
        s += __shfl_down_sync(0xffffffffu, s, off);
        q += __shfl_down_sync(0xffffffffu, q, off);
    }
    if ((t & 31) == 0) { ss[t >> 5] = s; qq[t >> 5] = q; }
    __syncthreads();
    if (t == 0) {
        s = 0.f; q = 0.f;
#pragma unroll
        for (int i = 0; i < 8; i++) { s += ss[i]; q += qq[i]; }
        const float inv_n = 1.0f / (float)N_NODES;
        float mean = s * inv_n;
        float var  = q * inv_n - mean * mean;
        float isd  = rsqrtf(var + BN_EPS);
        float sc   = __ldg(&bn_gamma[o]) * isd;
        g_scale[o] = sc;
        g_shift[o] = __ldg(&bn_beta[o]) - mean * sc;
    }
}

// ---------------- kernel 4: in-place normalize ----------------
__global__ void k_norm(float* __restrict__ h) {
    const size_t total = (size_t)N_NODES * F;
    size_t i = ((size_t)blockIdx.x * blockDim.x + threadIdx.x) * 4;
    if (i >= total) return;
    int o = (int)(i & (F - 1));
    float4 v  = *reinterpret_cast<float4*>(h + i);
    float4 sc = *reinterpret_cast<const float4*>(g_scale + o);
    float4 sh = *reinterpret_cast<const float4*>(g_shift + o);
    v.x = v.x * sc.x + sh.x;
    v.y = v.y * sc.y + sh.y;
    v.z = v.z * sc.z + sh.z;
    v.w = v.w * sc.w + sh.w;
    *reinterpret_cast<float4*>(h + i) = v;
}

// ---------------- launch (single stream) ----------------
extern "C" void kernel_launch(void* const* d_in, const int* in_sizes, int n_in,
                              void* d_out, int out_size) {
    const float* x        = (const float*)d_in[0];
    const int*   adj_row  = (const int*)  d_in[1];
    const int*   adj_col  = (const int*)  d_in[2];
    const float* adj_val  = (const float*)d_in[3];
    const float* fc_w     = (const float*)d_in[4];
    const float* fc_b     = (const float*)d_in[5];
    const float* bn_gamma = (const float*)d_in[6];
    const float* bn_beta  = (const float*)d_in[7];
    float* out = (float*)d_out;

    k_rowptr<<<(N_EDGES + 255) / 256, 256>>>(adj_row);
    k_gemm<<<GRID2, 256>>>(x, fc_w);
    k_spmm<<<NB_SPMM, 256>>>(adj_col, adj_val, fc_b, out);
    k_stats<<<F, 256>>>(bn_gamma, bn_beta);
    k_norm<<<(N_NODES * F / 4 + 255) / 256, 256>>>(out);
}

// round 10
// speedup vs baseline: 1.5801x; 1.3973x over previous
#include <cuda_runtime.h>
#include <cuda_fp16.h>
#include <mma.h>

using namespace nvcuda;

#define N_NODES 100000
#define N_EDGES 1600000
#define F 128
#define NB_GEMM 1563           // ceil(100000 / 64)
#define NB_SPMM 1480           // spmm blocks (grid-stride, 8 warps each)
#define BN_EPS 1e-5f

// -------- scratch (static device allocations are allowed) --------
__device__ int      g_row_ptr[N_NODES + 1];
__device__ __half   g_wh[F * F];                   // W in fp16 (32 KB)
__device__ __half   g_y[(size_t)N_NODES * F];      // y = x @ W^T fp16 (25.6 MB)
__device__ float    g_psum[(size_t)NB_SPMM * F];   // [block][feature], coalesced
__device__ float    g_psq [(size_t)NB_SPMM * F];
__device__ float    g_scale[F];
__device__ float    g_shift[F];

// ---------------- kernel 0a: row_ptr via boundary scatter ----------------
__global__ void k_rowptr(const int* __restrict__ adj_row) {
    int e = blockIdx.x * blockDim.x + threadIdx.x;
    if (e >= N_EDGES) return;
    int r1 = __ldg(&adj_row[e]);
    if (e == 0) {
        for (int r = 0; r <= r1; r++) g_row_ptr[r] = 0;
    }
    int r2 = (e + 1 < N_EDGES) ? __ldg(&adj_row[e + 1]) : N_NODES;
    for (int r = r1 + 1; r <= r2; r++) g_row_ptr[r] = e + 1;
}

// ---------------- kernel 0b: W -> fp16 ----------------
__global__ void k_wh(const float* __restrict__ fc_w) {
    int i = (blockIdx.x * blockDim.x + threadIdx.x) * 4;   // 4096 float4
    if (i >= F * F) return;
    float4 v = *reinterpret_cast<const float4*>(fc_w + i);
    __half2* dst = reinterpret_cast<__half2*>(g_wh + i);
    dst[0] = __floats2half2_rn(v.x, v.y);
    dst[1] = __floats2half2_rn(v.z, v.w);
}

// ------------- kernel 1: tensor-core GEMM y = x @ W^T (fp16 in/out, fp32 acc) -----
// block = 128 threads (4 warps), 64 nodes; warp owns 16 rows.
#define XS_LD 136              // padded lda (half) -> conflict-free ldmatrix
#define ST_LD 20               // per-warp staging pad (float)
__global__ void __launch_bounds__(128)
k_gemm_tc(const float* __restrict__ x) {
    __shared__ __half xs[64 * XS_LD];          // 17 KB
    __shared__ float  stage[4][16 * ST_LD];    // 5 KB per-warp staging

    const int t    = threadIdx.x;
    const int warp = t >> 5;
    const int lane = t & 31;
    const int n0   = blockIdx.x * 64;
    const int nv   = min(64, N_NODES - n0);

    // load x tile (fp32) -> smem fp16, rows >= nv zero-filled
#pragma unroll
    for (int i = 0; i < 16; i++) {
        int idx = i * 128 + t;                 // float4 index 0..2047
        int r = idx >> 5, c4 = idx & 31;
        float4 v = (r < nv)
            ? __ldg(&reinterpret_cast<const float4*>(x)[(size_t)(n0 + r) * 32 + c4])
            : make_float4(0.f, 0.f, 0.f, 0.f);
        __half2* dst = reinterpret_cast<__half2*>(xs + r * XS_LD + c4 * 4);
        dst[0] = __floats2half2_rn(v.x, v.y);
        dst[1] = __floats2half2_rn(v.z, v.w);
    }
    __syncthreads();

    wmma::fragment<wmma::matrix_a, 16, 16, 16, __half, wmma::row_major> a[8];
#pragma unroll
    for (int k = 0; k < 8; k++)
        wmma::load_matrix_sync(a[k], xs + warp * 16 * XS_LD + k * 16, XS_LD);

    __half2* y2 = reinterpret_cast<__half2*>(g_y);

#pragma unroll
    for (int nt = 0; nt < 8; nt++) {
        wmma::fragment<wmma::accumulator, 16, 16, 16, float> c;
        wmma::fill_fragment(c, 0.0f);
#pragma unroll
        for (int k = 0; k < 8; k++) {
            wmma::fragment<wmma::matrix_b, 16, 16, 16, __half, wmma::col_major> b;
            wmma::load_matrix_sync(b, g_wh + nt * 16 * F + k * 16, F);
            wmma::mma_sync(c, a[k], b, c);
        }
        wmma::store_matrix_sync(stage[warp], c, ST_LD, wmma::mem_row_major);
        __syncwarp();
        // convert this warp's 16x16 tile to fp16 y
#pragma unroll
        for (int i = 0; i < 4; i++) {
            int e  = i * 32 + lane;            // 128 half2 in tile
            int r  = e >> 3, c2 = e & 7;
            int gr = warp * 16 + r;
            if (gr < nv) {
                float2 v = *reinterpret_cast<const float2*>(stage[warp] + r * ST_LD + c2 * 2);
                y2[(size_t)(n0 + gr) * 64 + nt * 8 + c2] = __floats2half2_rn(v.x, v.y);
            }
        }
        __syncwarp();
    }
}

// ------- kernel 2: SpMM over y (fp16) + bias -> d_out, register BN partials -------
// grid-stride warp-per-node; lane owns features [4*lane, 4*lane+4).
__global__ void __launch_bounds__(256)
k_spmm(const int*   __restrict__ adj_col,
       const float* __restrict__ adj_val,
       const float* __restrict__ fc_b,
       float*       __restrict__ h_out) {
    __shared__ float4 red_s[8][32];
    __shared__ float4 red_q[8][32];

    const int wid  = threadIdx.x >> 5;
    const int lane = threadIdx.x & 31;
    const int gw   = blockIdx.x * 8 + wid;
    const int nw   = gridDim.x * 8;
    const uint2* yv = reinterpret_cast<const uint2*>(g_y);
    const float4 bb = __ldg(&reinterpret_cast<const float4*>(fc_b)[lane]);

    float4 bs = make_float4(0.f, 0.f, 0.f, 0.f);
    float4 bq = make_float4(0.f, 0.f, 0.f, 0.f);

    for (int n = gw; n < N_NODES; n += nw) {
        const int s = g_row_ptr[n];
        const int e = g_row_ptr[n + 1];

        float4 acc = make_float4(0.f, 0.f, 0.f, 0.f);
        int k = s;
        for (; k + 16 <= e; k += 16) {
            int col = 0; float val = 0.f;
            if (lane < 16) {
                col = __ldg(&adj_col[k + lane]);
                val = __ldg(&adj_val[k + lane]);
            }
#pragma unroll
            for (int j = 0; j < 16; j++) {
                int   c = __shfl_sync(0xffffffffu, col, j);
                float v = __shfl_sync(0xffffffffu, val, j);
                uint2 raw = __ldg(&yv[(size_t)c * 32 + lane]);
                float2 f0 = __half22float2(*reinterpret_cast<__half2*>(&raw.x));
                float2 f1 = __half22float2(*reinterpret_cast<__half2*>(&raw.y));
                acc.x += v * f0.x; acc.y += v * f0.y;
                acc.z += v * f1.x; acc.w += v * f1.y;
            }
        }
        if (k < e) {
            int rem = e - k;                   // 1..15
            int col = 0; float val = 0.f;
            if (lane < rem) {
                col = __ldg(&adj_col[k + lane]);
                val = __ldg(&adj_val[k + lane]);
            }
#pragma unroll
            for (int j = 0; j < 15; j++) {
                if (j < rem) {
                    int   c = __shfl_sync(0xffffffffu, col, j);
                    float v = __shfl_sync(0xffffffffu, val, j);
                    uint2 raw = __ldg(&yv[(size_t)c * 32 + lane]);
                    float2 f0 = __half22float2(*reinterpret_cast<__half2*>(&raw.x));
                    float2 f1 = __half22float2(*reinterpret_cast<__half2*>(&raw.y));
                    acc.x += v * f0.x; acc.y += v * f0.y;
                    acc.z += v * f1.x; acc.w += v * f1.y;
                }
            }
        }

        acc.x += bb.x; acc.y += bb.y; acc.z += bb.z; acc.w += bb.w;
        reinterpret_cast<float4*>(h_out)[(size_t)n * 32 + lane] = acc;

        bs.x += acc.x; bs.y += acc.y; bs.z += acc.z; bs.w += acc.w;
        bq.x += acc.x * acc.x; bq.y += acc.y * acc.y;
        bq.z += acc.z * acc.z; bq.w += acc.w * acc.w;
    }

    // one block-level reduction at the end; coalesced [block][f] store
    red_s[wid][lane] = bs;
    red_q[wid][lane] = bq;
    __syncthreads();
    if (wid == 0) {
        float4 s4 = red_s[0][lane], q4 = red_q[0][lane];
#pragma unroll
        for (int i = 1; i < 8; i++) {
            float4 a = red_s[i][lane], b = red_q[i][lane];
            s4.x += a.x; s4.y += a.y; s4.z += a.z; s4.w += a.w;
            q4.x += b.x; q4.y += b.y; q4.z += b.z; q4.w += b.w;
        }
        reinterpret_cast<float4*>(g_psum)[blockIdx.x * 32 + lane] = s4;
        reinterpret_cast<float4*>(g_psq )[blockIdx.x * 32 + lane] = q4;
    }
}

// ---------------- kernel 3: finalize BN stats ----------------
// one block per feature; 256 threads reduce NB_SPMM partials.
__global__ void __launch_bounds__(256)
k_stats(const float* __restrict__ bn_gamma,
        const float* __restrict__ bn_beta) {
    __shared__ float ss[8], qq[8];
    const int o = blockIdx.x;
    const int t = threadIdx.x;

    float s = 0.f, q = 0.f;
    for (int b = t; b < NB_SPMM; b += 256) {
        s += __ldg(&g_psum[(size_t)b * F + o]);
        q += __ldg(&g_psq [(size_t)b * F + o]);
    }
#pragma unroll
    for (int off = 16; off; off >>= 1) {
        s += __shfl_down_sync(0xffffffffu, s, off);
        q += __shfl_down_sync(0xffffffffu, q, off);
    }
    if ((t & 31) == 0) { ss[t >> 5] = s; qq[t >> 5] = q; }
    __syncthreads();
    if (t == 0) {
        s = 0.f; q = 0.f;
#pragma unroll
        for (int i = 0; i < 8; i++) { s += ss[i]; q += qq[i]; }
        const float inv_n = 1.0f / (float)N_NODES;
        float mean = s * inv_n;
        float var  = q * inv_n - mean * mean;
        float isd  = rsqrtf(var + BN_EPS);
        float sc   = __ldg(&bn_gamma[o]) * isd;
        g_scale[o] = sc;
        g_shift[o] = __ldg(&bn_beta[o]) - mean * sc;
    }
}

// ---------------- kernel 4: in-place normalize ----------------
__global__ void k_norm(float* __restrict__ h) {
    const size_t total = (size_t)N_NODES * F;
    size_t i = ((size_t)blockIdx.x * blockDim.x + threadIdx.x) * 4;
    if (i >= total) return;
    int o = (int)(i & (F - 1));
    float4 v  = *reinterpret_cast<float4*>(h + i);
    float4 sc = *reinterpret_cast<const float4*>(g_scale + o);
    float4 sh = *reinterpret_cast<const float4*>(g_shift + o);
    v.x = v.x * sc.x + sh.x;
    v.y = v.y * sc.y + sh.y;
    v.z = v.z * sc.z + sh.z;
    v.w = v.w * sc.w + sh.w;
    *reinterpret_cast<float4*>(h + i) = v;
}

// ---------------- launch (single stream) ----------------
extern "C" void kernel_launch(void* const* d_in, const int* in_sizes, int n_in,
                              void* d_out, int out_size) {
    const float* x        = (const float*)d_in[0];
    const int*   adj_row  = (const int*)  d_in[1];
    const int*   adj_col  = (const int*)  d_in[2];
    const float* adj_val  = (const float*)d_in[3];
    const float* fc_w     = (const float*)d_in[4];
    const float* fc_b     = (const float*)d_in[5];
    const float* bn_gamma = (const float*)d_in[6];
    const float* bn_beta  = (const float*)d_in[7];
    float* out = (float*)d_out;

    k_rowptr<<<(N_EDGES + 255) / 256, 256>>>(adj_row);
    k_wh<<<(F * F / 4 + 255) / 256, 256>>>(fc_w);
    k_gemm_tc<<<NB_GEMM, 128>>>(x);
    k_spmm<<<NB_SPMM, 256>>>(adj_col, adj_val, fc_b, out);
    k_stats<<<F, 256>>>(bn_gamma, bn_beta);
    k_norm<<<(N_NODES * F / 4 + 255) / 256, 256>>>(out);
}